// round 7
// baseline (speedup 1.0000x reference)
#include <cuda_runtime.h>
#include <math.h>

// Shapes (fixed for this problem)
#define NB   4
#define C    512
#define HW   4096
#define GRP  32
#define CPG  16            // channels per group
#define D3   1536          // 3*C
#define EPS  1e-5f

// ---------------- scratch (device globals; no allocation allowed) ----------------
// NEVER referenced from host code (host code taking their address yields the
// host shadow symbol -> UB; on GB300 ATS it silently reads host memory).
// All access goes through buf_ptr() in device code.
__device__ float g_seq   [(size_t)NB * HW * C];     // [n][s][c]
__device__ float g_qkv   [(size_t)NB * HW * D3];    // [n][s][3c]
__device__ float g_scores[(size_t)NB * HW * HW];    // [n][s][t]
__device__ float g_att   [(size_t)NB * HW * C];     // [n][s][c]
__device__ float g_proj  [(size_t)NB * HW * C];     // [n][s][c]
__device__ float g_mean  [NB * GRP];
__device__ float g_rstd  [NB * GRP];

#define BUF_SEQ    0
#define BUF_QKV    1
#define BUF_SCORES 2
#define BUF_ATT    3
#define BUF_PROJ   4

__device__ __forceinline__ float* buf_ptr(int id) {
    switch (id) {
        case BUF_SEQ:    return g_seq;
        case BUF_QKV:    return g_qkv;
        case BUF_SCORES: return g_scores;
        case BUF_ATT:    return g_att;
        default:         return g_proj;
    }
}

// ---------------- GroupNorm statistics ----------------
// grid (GRP, NB), 256 threads. Group g = channels [g*16, (g+1)*16), 16*4096 floats.
__global__ void gn_stats_kernel(const float* __restrict__ x) {
    int g = blockIdx.x, n = blockIdx.y;
    const float4* p = (const float4*)(x + ((size_t)n * C + (size_t)g * CPG) * HW);
    float s = 0.f, s2 = 0.f;
    for (int i = threadIdx.x; i < (CPG * HW) / 4; i += 256) {
        float4 v = p[i];
        s  += v.x + v.y + v.z + v.w;
        s2 += v.x * v.x + v.y * v.y + v.z * v.z + v.w * v.w;
    }
    __shared__ float shs[8], shs2[8];
    for (int o = 16; o > 0; o >>= 1) {
        s  += __shfl_down_sync(0xffffffffu, s,  o);
        s2 += __shfl_down_sync(0xffffffffu, s2, o);
    }
    if ((threadIdx.x & 31) == 0) { shs[threadIdx.x >> 5] = s; shs2[threadIdx.x >> 5] = s2; }
    __syncthreads();
    if (threadIdx.x == 0) {
        s = 0.f; s2 = 0.f;
        for (int i = 0; i < 8; i++) { s += shs[i]; s2 += shs2[i]; }
        const float invn = 1.f / (float)(CPG * HW);
        float m   = s * invn;
        float var = s2 * invn - m * m;
        g_mean[n * GRP + g] = m;
        g_rstd[n * GRP + g] = rsqrtf(var + EPS);
    }
}

// ---------------- naive normalize + transpose ----------------
// One thread per element of x's layout [n][c][s].
// g_seq[n][s][c] = (x[n][c][s] - mean[n,g]) * rstd[n,g] * gns[c] + gnb[c]
__global__ void gn_apply_naive(const float* __restrict__ x,
                               const float* __restrict__ gns,
                               const float* __restrict__ gnb) {
    size_t i = (size_t)blockIdx.x * blockDim.x + threadIdx.x;
    if (i >= (size_t)NB * C * HW) return;
    int s = (int)(i % HW);
    size_t t = i / HW;
    int c = (int)(t % C);
    int n = (int)(t / C);
    float m = g_mean[n * GRP + (c >> 4)];
    float r = g_rstd[n * GRP + (c >> 4)];
    g_seq[((size_t)n * HW + s) * C + c] = (x[i] - m) * r * gns[c] + gnb[c];
}

// ---------------- tiled SGEMM (single-buffered) ----------------
// Out[m][n] = alpha * sum_k A[m][k] * (TRANSB ? B[n][k] : B[k][n]) + bias[n]
// A/B resolved from internal scratch (id>=0, +element offset) or external pointer.
// Output always an internal buffer. BM=BN=128, BK=16, 256 threads, 8x8/thread.
template <bool TRANSB>
__global__ void __launch_bounds__(256, 2) sgemm_kernel(
    int aid, long long aoff, const float* Aext,
    int bid, long long boff, const float* Bext,
    int cid,
    int K, int lda, int ldb, int ldc,
    long long strideA, long long strideB, long long strideC,
    const float* bias, float alpha) {

    __shared__ float As[16][128];
    __shared__ float Bs[16][128];

    const float* A = (aid >= 0) ? (const float*)(buf_ptr(aid) + aoff) : Aext;
    const float* B = (bid >= 0) ? (const float*)(buf_ptr(bid) + boff) : Bext;
    float* Cc = buf_ptr(cid);

    int nb = blockIdx.z;
    A  += (size_t)nb * strideA;
    B  += (size_t)nb * strideB;
    Cc += (size_t)nb * strideC;

    int m0 = blockIdx.y * 128;
    int n0 = blockIdx.x * 128;
    int tid = threadIdx.x;
    int tx = tid & 15, ty = tid >> 4;

    float acc[8][8];
    #pragma unroll
    for (int i = 0; i < 8; i++)
        #pragma unroll
        for (int j = 0; j < 8; j++) acc[i][j] = 0.f;

    for (int k0 = 0; k0 < K; k0 += 16) {
        #pragma unroll
        for (int l = 0; l < 2; l++) {
            int f = tid + l * 256;
            int row = f >> 2, kc = (f & 3) * 4;
            float4 v = *(const float4*)&A[(size_t)(m0 + row) * lda + k0 + kc];
            As[kc + 0][row] = v.x; As[kc + 1][row] = v.y;
            As[kc + 2][row] = v.z; As[kc + 3][row] = v.w;
        }
        if (TRANSB) {
            #pragma unroll
            for (int l = 0; l < 2; l++) {
                int f = tid + l * 256;
                int row = f >> 2, kc = (f & 3) * 4;
                float4 v = *(const float4*)&B[(size_t)(n0 + row) * ldb + k0 + kc];
                Bs[kc + 0][row] = v.x; Bs[kc + 1][row] = v.y;
                Bs[kc + 2][row] = v.z; Bs[kc + 3][row] = v.w;
            }
        } else {
            #pragma unroll
            for (int l = 0; l < 2; l++) {
                int f = tid + l * 256;
                int kr = f >> 5, nc = (f & 31) * 4;
                *(float4*)&Bs[kr][nc] =
                    *(const float4*)&B[(size_t)(k0 + kr) * ldb + n0 + nc];
            }
        }
        __syncthreads();

        #pragma unroll
        for (int kk = 0; kk < 16; kk++) {
            float a[8], b[8];
            *(float4*)&a[0] = *(const float4*)&As[kk][ty * 8];
            *(float4*)&a[4] = *(const float4*)&As[kk][ty * 8 + 4];
            *(float4*)&b[0] = *(const float4*)&Bs[kk][tx * 8];
            *(float4*)&b[4] = *(const float4*)&Bs[kk][tx * 8 + 4];
            #pragma unroll
            for (int i = 0; i < 8; i++)
                #pragma unroll
                for (int j = 0; j < 8; j++)
                    acc[i][j] += a[i] * b[j];
        }
        __syncthreads();
    }

    #pragma unroll
    for (int i = 0; i < 8; i++) {
        int m = m0 + ty * 8 + i;
        #pragma unroll
        for (int j = 0; j < 8; j += 4) {
            int cn = n0 + tx * 8 + j;
            float4 o;
            o.x = acc[i][j + 0] * alpha;
            o.y = acc[i][j + 1] * alpha;
            o.z = acc[i][j + 2] * alpha;
            o.w = acc[i][j + 3] * alpha;
            if (bias) {
                o.x += bias[cn + 0]; o.y += bias[cn + 1];
                o.z += bias[cn + 2]; o.w += bias[cn + 3];
            }
            *(float4*)&Cc[(size_t)m * ldc + cn] = o;
        }
    }
}

// ---------------- simple softmax over g_scores rows, one block per row ----------
__global__ void softmax_kernel() {
    __shared__ float red[8];
    size_t r = blockIdx.x;
    float* p = g_scores + r * (size_t)HW;
    int tid = threadIdx.x;

    float mx = -INFINITY;
    for (int i = tid; i < HW; i += 256) mx = fmaxf(mx, p[i]);
    for (int o = 16; o > 0; o >>= 1) mx = fmaxf(mx, __shfl_down_sync(0xffffffffu, mx, o));
    if ((tid & 31) == 0) red[tid >> 5] = mx;
    __syncthreads();
    if (tid == 0) {
        mx = red[0];
        for (int i = 1; i < 8; i++) mx = fmaxf(mx, red[i]);
        red[0] = mx;
    }
    __syncthreads();
    mx = red[0];
    __syncthreads();

    float sum = 0.f;
    for (int i = tid; i < HW; i += 256) {
        float e = __expf(p[i] - mx);
        p[i] = e;
        sum += e;
    }
    for (int o = 16; o > 0; o >>= 1) sum += __shfl_down_sync(0xffffffffu, sum, o);
    if ((tid & 31) == 0) red[tid >> 5] = sum;
    __syncthreads();
    if (tid == 0) {
        sum = 0.f;
        for (int i = 0; i < 8; i++) sum += red[i];
        red[0] = sum;
    }
    __syncthreads();
    float inv = 1.f / red[0];

    for (int i = tid; i < HW; i += 256) p[i] *= inv;
}

// ---------------- naive epilogue: out[n][c][s] = g_proj[n][s][c] + x[n][c][s] ---
__global__ void out_epilogue_naive(const float* __restrict__ x, float* __restrict__ y) {
    size_t i = (size_t)blockIdx.x * blockDim.x + threadIdx.x;  // over [n][c][s]
    if (i >= (size_t)NB * C * HW) return;
    int s = (int)(i % HW);
    size_t t = i / HW;
    int c = (int)(t % C);
    int n = (int)(t / C);
    y[i] = g_proj[((size_t)n * HW + s) * C + c] + x[i];
}

extern "C" void kernel_launch(void* const* d_in, const int* in_sizes, int n_in,
                              void* d_out, int out_size) {
    // Resolve inputs by element count; the three 512-vectors keep encounter order.
    const float* x = 0; const float* w_in = 0; const float* w_out = 0; const float* b_in = 0;
    const float* v512[3] = {0, 0, 0}; int n512 = 0;
    for (int i = 0; i < n_in; i++) {
        const float* p = (const float*)d_in[i];
        switch (in_sizes[i]) {
            case 8388608: x = p; break;      // x (4,512,64,64)
            case 786432:  w_in = p; break;   // w_in (1536,512)
            case 262144:  w_out = p; break;  // w_out (512,512)
            case 1536:    b_in = p; break;   // b_in
            case 512:     if (n512 < 3) v512[n512++] = p; break;
            default: break;
        }
    }
    const float* gns   = v512[0];   // gn_scale
    const float* gnb   = v512[1];   // gn_bias
    const float* b_out = v512[2];   // b_out
    float* out = (float*)d_out;

    const size_t TOT = (size_t)NB * C * HW;

    // 1) GroupNorm stats
    gn_stats_kernel<<<dim3(GRP, NB), 256>>>(x);

    // 2) normalize + transpose -> g_seq[n,s,c]
    gn_apply_naive<<<(unsigned)((TOT + 255) / 256), 256>>>(x, gns, gnb);

    // 3) qkv[n,s,d] = sum_c seq[n,s,c] * w_in[d,c] + b_in[d]
    sgemm_kernel<true><<<dim3(D3 / 128, HW / 128, NB), 256>>>(
        BUF_SEQ, 0LL, (const float*)0,  -1, 0LL, w_in,  BUF_QKV,
        C, C, C, D3,
        (long long)HW * C, 0LL, (long long)HW * D3, b_in, 1.0f);

    // 4) scores[n,s,t] = (1/sqrt(C)) * sum_c q[n,s,c] * k[n,t,c]
    sgemm_kernel<true><<<dim3(HW / 128, HW / 128, NB), 256>>>(
        BUF_QKV, 0LL, (const float*)0,  BUF_QKV, (long long)C, (const float*)0,  BUF_SCORES,
        C, D3, D3, HW,
        (long long)HW * D3, (long long)HW * D3, (long long)HW * HW,
        (const float*)0, rsqrtf((float)C));

    // 5) softmax over t
    softmax_kernel<<<NB * HW, 256>>>();

    // 6) att[n,s,c] = sum_t attn[n,s,t] * v[n,t,c]
    sgemm_kernel<false><<<dim3(C / 128, HW / 128, NB), 256>>>(
        BUF_SCORES, 0LL, (const float*)0,  BUF_QKV, (long long)(2 * C), (const float*)0,  BUF_ATT,
        HW, HW, D3, C,
        (long long)HW * HW, (long long)HW * D3, (long long)HW * C,
        (const float*)0, 1.0f);

    // 7) proj[n,s,d] = sum_c att[n,s,c] * w_out[d,c] + b_out[d]
    sgemm_kernel<true><<<dim3(C / 128, HW / 128, NB), 256>>>(
        BUF_ATT, 0LL, (const float*)0,  -1, 0LL, w_out,  BUF_PROJ,
        C, C, C, C,
        (long long)HW * C, 0LL, (long long)HW * C, b_out, 1.0f);

    // 8) out[n][c][s] = proj[n][s][c] + x[n][c][s]
    out_epilogue_naive<<<(unsigned)((TOT + 255) / 256), 256>>>(x, out);
}

// round 9
// speedup vs baseline: 2.7644x; 2.7644x over previous
#include <cuda_runtime.h>
#include <cuda_bf16.h>
#include <math.h>
#include <string.h>

// Shapes (fixed)
#define NB   4
#define C    512
#define HW   4096
#define GRP  32
#define CPG  16
#define D3   1536
#define EPS  1e-5f

// ---------------- scratch (device globals; resolved ONLY in device code) ----------
__device__ __nv_bfloat16 g_seq_bf [(size_t)NB * HW * C];
__device__ __nv_bfloat16 g_win_bf [(size_t)D3 * C];
__device__ __nv_bfloat16 g_wout_bf[(size_t)C * C];
__device__ __nv_bfloat16 g_qkv_bf [(size_t)NB * HW * D3];
__device__ __nv_bfloat16 g_attn_bf[(size_t)NB * HW * HW];
__device__ __nv_bfloat16 g_att_bf [(size_t)NB * HW * C];
__device__ float         g_scores [(size_t)NB * HW * HW];
__device__ float         g_proj   [(size_t)NB * HW * C];
__device__ float         g_mean   [NB * GRP];
__device__ float         g_rstd   [NB * GRP];

#define BF_SEQ  0
#define BF_WIN  1
#define BF_WOUT 2
#define BF_QKV  3
#define BF_ATTN 4
#define BF_ATT  5
#define FP_SCORES 0
#define FP_PROJ   1

__device__ __forceinline__ __nv_bfloat16* bufb(int id) {
    switch (id) {
        case BF_SEQ:  return g_seq_bf;
        case BF_WIN:  return g_win_bf;
        case BF_WOUT: return g_wout_bf;
        case BF_QKV:  return g_qkv_bf;
        case BF_ATTN: return g_attn_bf;
        default:      return g_att_bf;
    }
}
__device__ __forceinline__ float* buff(int id) {
    return (id == FP_SCORES) ? g_scores : g_proj;
}

// ---------------- GroupNorm stats ----------------
__global__ void gn_stats_kernel(const float* __restrict__ x) {
    int g = blockIdx.x, n = blockIdx.y;
    const float4* p = (const float4*)(x + ((size_t)n * C + (size_t)g * CPG) * HW);
    float s = 0.f, s2 = 0.f;
    for (int i = threadIdx.x; i < (CPG * HW) / 4; i += 256) {
        float4 v = p[i];
        s  += v.x + v.y + v.z + v.w;
        s2 += v.x * v.x + v.y * v.y + v.z * v.z + v.w * v.w;
    }
    __shared__ float shs[8], shs2[8];
    for (int o = 16; o > 0; o >>= 1) {
        s  += __shfl_down_sync(0xffffffffu, s,  o);
        s2 += __shfl_down_sync(0xffffffffu, s2, o);
    }
    if ((threadIdx.x & 31) == 0) { shs[threadIdx.x >> 5] = s; shs2[threadIdx.x >> 5] = s2; }
    __syncthreads();
    if (threadIdx.x == 0) {
        s = 0.f; s2 = 0.f;
        for (int i = 0; i < 8; i++) { s += shs[i]; s2 += shs2[i]; }
        const float invn = 1.f / (float)(CPG * HW);
        float m   = s * invn;
        float var = s2 * invn - m * m;
        g_mean[n * GRP + g] = m;
        g_rstd[n * GRP + g] = rsqrtf(var + EPS);
    }
}

// ---------------- normalize + transpose -> bf16 seq[n,s,c] ----------------
__global__ void gn_apply_naive(const float* __restrict__ x,
                               const float* __restrict__ gns,
                               const float* __restrict__ gnb) {
    size_t i = (size_t)blockIdx.x * blockDim.x + threadIdx.x;
    if (i >= (size_t)NB * C * HW) return;
    int s = (int)(i % HW);
    size_t t = i / HW;
    int c = (int)(t % C);
    int n = (int)(t / C);
    float m = g_mean[n * GRP + (c >> 4)];
    float r = g_rstd[n * GRP + (c >> 4)];
    float v = (x[i] - m) * r * gns[c] + gnb[c];
    g_seq_bf[((size_t)n * HW + s) * C + c] = __float2bfloat16(v);
}

// ---------------- fp32 -> bf16 weight convert ----------------
__global__ void convert_kernel(const float* __restrict__ src, int dstid, int count) {
    int i = blockIdx.x * blockDim.x + threadIdx.x;
    if (i < count) bufb(dstid)[i] = __float2bfloat16(src[i]);
}

// ---------------- bf16 tensor-core GEMM (mma.sync m16n8k16) ----------------
// Out[m][n] = alpha * sum_k A[m][k] * (TRANSB ? B[n][k] : B[k][n]) + bias[n]
// BM=BN=128, BK=32, 256 threads (8 warps as 4x2), warp tile 32x64.
#define SKB 40   // smem row stride in halves (32 + 8 pad) -> ldmatrix conflict-free

template <bool TRANSB, bool OUT_BF16>
__global__ void __launch_bounds__(256, 2) mma_gemm(
    int aid, long long aoff, int bid, long long boff, int cid,
    int K, int lda, int ldb, int ldc,
    long long sA, long long sB, long long sC,
    const float* bias, float alpha) {

    __shared__ __nv_bfloat16 As[128 * SKB];
    __shared__ __nv_bfloat16 Bs[128 * SKB];

    const __nv_bfloat16* A = bufb(aid) + aoff + (size_t)blockIdx.z * sA;
    const __nv_bfloat16* B = bufb(bid) + boff + (size_t)blockIdx.z * sB;

    int m0 = blockIdx.y * 128;
    int n0 = blockIdx.x * 128;
    int tid  = threadIdx.x;
    int warp = tid >> 5, lane = tid & 31;
    int wm = (warp & 3) * 32;       // warp row offset
    int wn = (warp >> 2) * 64;      // warp col offset
    int lrow = lane & 7, lgrp = lane >> 3;

    // precomputed ldmatrix smem byte-addresses
    unsigned as_base = (unsigned)__cvta_generic_to_shared(As);
    unsigned bs_base = (unsigned)__cvta_generic_to_shared(Bs);
    unsigned aaddr[2][2], baddr[2][4];
    #pragma unroll
    for (int ks = 0; ks < 2; ks++) {
        #pragma unroll
        for (int mf = 0; mf < 2; mf++) {
            int row = wm + mf * 16 + (lgrp & 1) * 8 + lrow;
            int kof = ks * 16 + (lgrp >> 1) * 8;
            aaddr[ks][mf] = as_base + (unsigned)(row * SKB + kof) * 2u;
        }
        #pragma unroll
        for (int np = 0; np < 4; np++) {
            int nn  = wn + np * 16 + (lgrp >> 1) * 8 + lrow;
            int kof = ks * 16 + (lgrp & 1) * 8;
            baddr[ks][np] = bs_base + (unsigned)(nn * SKB + kof) * 2u;
        }
    }

    float acc[2][8][4];
    #pragma unroll
    for (int mf = 0; mf < 2; mf++)
        #pragma unroll
        for (int nf = 0; nf < 8; nf++)
            #pragma unroll
            for (int r = 0; r < 4; r++) acc[mf][nf][r] = 0.f;

    for (int k0 = 0; k0 < K; k0 += 32) {
        // --- load A tile: As[row][k] from A[m0+row][k0+..]
        #pragma unroll
        for (int l = 0; l < 2; l++) {
            int idx = tid + l * 256;            // 0..511
            int row = idx >> 2, ch = (idx & 3) * 8;
            *(uint4*)&As[row * SKB + ch] =
                *(const uint4*)&A[(size_t)(m0 + row) * lda + k0 + ch];
        }
        // --- load B tile into Bs[n][k]
        if (TRANSB) {
            #pragma unroll
            for (int l = 0; l < 2; l++) {
                int idx = tid + l * 256;
                int row = idx >> 2, ch = (idx & 3) * 8;
                *(uint4*)&Bs[row * SKB + ch] =
                    *(const uint4*)&B[(size_t)(n0 + row) * ldb + k0 + ch];
            }
        } else {
            #pragma unroll
            for (int l = 0; l < 2; l++) {
                int idx = tid + l * 256;        // 0..511
                int kr = idx >> 4;              // 0..31
                int nc = (idx & 15) * 8;        // 0..120
                uint4 v = *(const uint4*)&B[(size_t)(k0 + kr) * ldb + n0 + nc];
                __nv_bfloat16 tmp[8];
                memcpy(tmp, &v, 16);
                #pragma unroll
                for (int j = 0; j < 8; j++)
                    Bs[(nc + j) * SKB + kr] = tmp[j];
            }
        }
        __syncthreads();

        #pragma unroll
        for (int ks = 0; ks < 2; ks++) {
            unsigned a[2][4], b[4][4];
            #pragma unroll
            for (int mf = 0; mf < 2; mf++)
                asm volatile("ldmatrix.sync.aligned.m8n8.x4.shared.b16 {%0,%1,%2,%3}, [%4];"
                             : "=r"(a[mf][0]), "=r"(a[mf][1]), "=r"(a[mf][2]), "=r"(a[mf][3])
                             : "r"(aaddr[ks][mf]));
            #pragma unroll
            for (int np = 0; np < 4; np++)
                asm volatile("ldmatrix.sync.aligned.m8n8.x4.shared.b16 {%0,%1,%2,%3}, [%4];"
                             : "=r"(b[np][0]), "=r"(b[np][1]), "=r"(b[np][2]), "=r"(b[np][3])
                             : "r"(baddr[ks][np]));
            #pragma unroll
            for (int mf = 0; mf < 2; mf++)
                #pragma unroll
                for (int np = 0; np < 4; np++) {
                    #pragma unroll
                    for (int h = 0; h < 2; h++) {
                        float* c = acc[mf][np * 2 + h];
                        asm volatile(
                            "mma.sync.aligned.m16n8k16.row.col.f32.bf16.bf16.f32 "
                            "{%0,%1,%2,%3}, {%4,%5,%6,%7}, {%8,%9}, {%0,%1,%2,%3};"
                            : "+f"(c[0]), "+f"(c[1]), "+f"(c[2]), "+f"(c[3])
                            : "r"(a[mf][0]), "r"(a[mf][1]), "r"(a[mf][2]), "r"(a[mf][3]),
                              "r"(b[np][h * 2]), "r"(b[np][h * 2 + 1]));
                    }
                }
        }
        __syncthreads();
    }

    // ---- epilogue ----
    #pragma unroll
    for (int mf = 0; mf < 2; mf++) {
        #pragma unroll
        for (int nf = 0; nf < 8; nf++) {
            int r0 = m0 + wm + mf * 16 + (lane >> 2);
            int cc = n0 + wn + nf * 8 + (lane & 3) * 2;
            float* c = acc[mf][nf];
            float b0 = 0.f, b1 = 0.f;
            if (bias) { b0 = bias[cc]; b1 = bias[cc + 1]; }
            float v0 = c[0] * alpha + b0, v1 = c[1] * alpha + b1;
            float v2 = c[2] * alpha + b0, v3 = c[3] * alpha + b1;
            if (OUT_BF16) {
                __nv_bfloat16* O = bufb(cid) + (size_t)blockIdx.z * sC;
                *(__nv_bfloat162*)&O[(size_t)r0 * ldc + cc] =
                    __nv_bfloat162(__float2bfloat16(v0), __float2bfloat16(v1));
                *(__nv_bfloat162*)&O[(size_t)(r0 + 8) * ldc + cc] =
                    __nv_bfloat162(__float2bfloat16(v2), __float2bfloat16(v3));
            } else {
                float* O = buff(cid) + (size_t)blockIdx.z * sC;
                *(float2*)&O[(size_t)r0 * ldc + cc] = make_float2(v0, v1);
                *(float2*)&O[(size_t)(r0 + 8) * ldc + cc] = make_float2(v2, v3);
            }
        }
    }
}

// ---------------- softmax: fp32 scores row -> bf16 attn row ----------------
__global__ void softmax_bf_kernel() {
    __shared__ float red[8];
    __shared__ float row[HW];  // 16 KB
    size_t r = blockIdx.x;
    const float* p = g_scores + r * (size_t)HW;
    __nv_bfloat16* o = g_attn_bf + r * (size_t)HW;
    int tid = threadIdx.x;

    float mx = -INFINITY;
    for (int i = tid; i < HW; i += 256) {
        float v = p[i];
        row[i] = v;
        mx = fmaxf(mx, v);
    }
    for (int of = 16; of > 0; of >>= 1) mx = fmaxf(mx, __shfl_down_sync(0xffffffffu, mx, of));
    if ((tid & 31) == 0) red[tid >> 5] = mx;
    __syncthreads();
    if (tid == 0) {
        mx = red[0];
        for (int i = 1; i < 8; i++) mx = fmaxf(mx, red[i]);
        red[0] = mx;
    }
    __syncthreads();
    mx = red[0];
    __syncthreads();

    float sum = 0.f;
    for (int i = tid; i < HW; i += 256) {
        float e = __expf(row[i] - mx);
        row[i] = e;
        sum += e;
    }
    for (int of = 16; of > 0; of >>= 1) sum += __shfl_down_sync(0xffffffffu, sum, of);
    if ((tid & 31) == 0) red[tid >> 5] = sum;
    __syncthreads();
    if (tid == 0) {
        sum = 0.f;
        for (int i = 0; i < 8; i++) sum += red[i];
        red[0] = sum;
    }
    __syncthreads();
    float inv = 1.f / red[0];

    for (int i = tid; i < HW; i += 256)
        o[i] = __float2bfloat16(row[i] * inv);
}

// ---------------- epilogue: out[n][c][s] = g_proj[n][s][c] + x[n][c][s] --------
__global__ void out_epilogue_naive(const float* __restrict__ x, float* __restrict__ y) {
    size_t i = (size_t)blockIdx.x * blockDim.x + threadIdx.x;
    if (i >= (size_t)NB * C * HW) return;
    int s = (int)(i % HW);
    size_t t = i / HW;
    int c = (int)(t % C);
    int n = (int)(t / C);
    y[i] = g_proj[((size_t)n * HW + s) * C + c] + x[i];
}

extern "C" void kernel_launch(void* const* d_in, const int* in_sizes, int n_in,
                              void* d_out, int out_size) {
    const float* x = 0; const float* w_in = 0; const float* w_out = 0; const float* b_in = 0;
    const float* v512[3] = {0, 0, 0}; int n512 = 0;
    for (int i = 0; i < n_in; i++) {
        const float* p = (const float*)d_in[i];
        switch (in_sizes[i]) {
            case 8388608: x = p; break;
            case 786432:  w_in = p; break;
            case 262144:  w_out = p; break;
            case 1536:    b_in = p; break;
            case 512:     if (n512 < 3) v512[n512++] = p; break;
            default: break;
        }
    }
    const float* gns   = v512[0];
    const float* gnb   = v512[1];
    const float* b_out = v512[2];
    float* out = (float*)d_out;

    const size_t TOT = (size_t)NB * C * HW;

    // 1) GroupNorm stats + apply (-> bf16 seq)
    gn_stats_kernel<<<dim3(GRP, NB), 256>>>(x);
    gn_apply_naive<<<(unsigned)((TOT + 255) / 256), 256>>>(x, gns, gnb);

    // weight converts
    convert_kernel<<<(D3 * C + 255) / 256, 256>>>(w_in, BF_WIN, D3 * C);
    convert_kernel<<<(C * C + 255) / 256, 256>>>(w_out, BF_WOUT, C * C);

    // 2) QKV: qkv[s,d] = seq[s,:] . w_in[d,:] + b_in  (bf16 out)
    mma_gemm<true, true><<<dim3(D3 / 128, HW / 128, NB), 256>>>(
        BF_SEQ, 0LL, BF_WIN, 0LL, BF_QKV,
        C, C, C, D3,
        (long long)HW * C, 0LL, (long long)HW * D3, b_in, 1.0f);

    // 3) scores[s,t] = (1/sqrt(C)) q[s,:].k[t,:]  (fp32 out)
    mma_gemm<true, false><<<dim3(HW / 128, HW / 128, NB), 256>>>(
        BF_QKV, 0LL, BF_QKV, (long long)C, FP_SCORES,
        C, D3, D3, HW,
        (long long)HW * D3, (long long)HW * D3, (long long)HW * HW,
        (const float*)0, rsqrtf((float)C));

    // 4) softmax -> bf16 attn
    softmax_bf_kernel<<<NB * HW, 256>>>();

    // 5) att[s,c] = sum_t attn[s,t] v[t,c]  (bf16 out)
    mma_gemm<false, true><<<dim3(C / 128, HW / 128, NB), 256>>>(
        BF_ATTN, 0LL, BF_QKV, (long long)(2 * C), BF_ATT,
        HW, HW, D3, C,
        (long long)HW * HW, (long long)HW * D3, (long long)HW * C,
        (const float*)0, 1.0f);

    // 6) proj[s,d] = att[s,:] . w_out[d,:] + b_out  (fp32 out)
    mma_gemm<true, false><<<dim3(C / 128, HW / 128, NB), 256>>>(
        BF_ATT, 0LL, BF_WOUT, 0LL, FP_PROJ,
        C, C, C, C,
        (long long)HW * C, 0LL, (long long)HW * C, b_out, 1.0f);

    // 7) out = transpose(proj) + x
    out_epilogue_naive<<<(unsigned)((TOT + 255) / 256), 256>>>(x, out);
}

// round 13
// speedup vs baseline: 5.0953x; 1.8432x over previous
#include <cuda_runtime.h>
#include <cuda_bf16.h>
#include <math.h>

// Shapes (fixed)
#define NB   4
#define C    512
#define HW   4096
#define GRP  32
#define CPG  16
#define D3   1536
#define EPS  1e-5f

// ---------------- scratch (device globals) ----------------
// RULE: these symbols are referenced ONLY inside device code. Host passes ids.
__device__ __nv_bfloat16 g_seq_bf [(size_t)NB * HW * C];
__device__ __nv_bfloat16 g_win_bf [(size_t)D3 * C];
__device__ __nv_bfloat16 g_wout_bf[(size_t)C * C];
__device__ __nv_bfloat16 g_qkv_bf [(size_t)NB * HW * D3];
__device__ __nv_bfloat16 g_attn_bf[(size_t)NB * HW * HW];   // scores, softmaxed in place
__device__ __nv_bfloat16 g_att_bf [(size_t)NB * HW * C];
__device__ float         g_proj   [(size_t)NB * HW * C];
__device__ float         g_mean   [NB * GRP];
__device__ float         g_rstd   [NB * GRP];

#define BF_SEQ  0
#define BF_WIN  1
#define BF_WOUT 2
#define BF_QKV  3
#define BF_ATTN 4
#define BF_ATT  5

__device__ __forceinline__ __nv_bfloat16* bufb(int id) {
    switch (id) {
        case BF_SEQ:  return g_seq_bf;
        case BF_WIN:  return g_win_bf;
        case BF_WOUT: return g_wout_bf;
        case BF_QKV:  return g_qkv_bf;
        case BF_ATTN: return g_attn_bf;
        default:      return g_att_bf;
    }
}
// fp32 output resolver (device-side!). id 0 -> g_proj.
__device__ __forceinline__ float* buff(int id) { return g_proj; }

// ---------------- cp.async helpers ----------------
__device__ __forceinline__ void cpa16(unsigned s, const void* g) {
    asm volatile("cp.async.cg.shared.global [%0], [%1], 16;" :: "r"(s), "l"(g));
}
__device__ __forceinline__ void cpa_commit() { asm volatile("cp.async.commit_group;"); }
template <int N>
__device__ __forceinline__ void cpa_wait() { asm volatile("cp.async.wait_group %0;" :: "n"(N)); }

// ---------------- GroupNorm stats ----------------
__global__ void gn_stats_kernel(const float* __restrict__ x) {
    int g = blockIdx.x, n = blockIdx.y;
    const float4* p = (const float4*)(x + ((size_t)n * C + (size_t)g * CPG) * HW);
    float s = 0.f, s2 = 0.f;
    for (int i = threadIdx.x; i < (CPG * HW) / 4; i += 256) {
        float4 v = p[i];
        s  += v.x + v.y + v.z + v.w;
        s2 += v.x * v.x + v.y * v.y + v.z * v.z + v.w * v.w;
    }
    __shared__ float shs[8], shs2[8];
    for (int o = 16; o > 0; o >>= 1) {
        s  += __shfl_down_sync(0xffffffffu, s,  o);
        s2 += __shfl_down_sync(0xffffffffu, s2, o);
    }
    if ((threadIdx.x & 31) == 0) { shs[threadIdx.x >> 5] = s; shs2[threadIdx.x >> 5] = s2; }
    __syncthreads();
    if (threadIdx.x == 0) {
        s = 0.f; s2 = 0.f;
        for (int i = 0; i < 8; i++) { s += shs[i]; s2 += shs2[i]; }
        const float invn = 1.f / (float)(CPG * HW);
        float m   = s * invn;
        float var = s2 * invn - m * m;
        g_mean[n * GRP + g] = m;
        g_rstd[n * GRP + g] = rsqrtf(var + EPS);
    }
}

// ---------------- normalize + transpose -> bf16 seq[n,s,c] ----------------
__global__ void gn_apply_naive(const float* __restrict__ x,
                               const float* __restrict__ gns,
                               const float* __restrict__ gnb) {
    size_t i = (size_t)blockIdx.x * blockDim.x + threadIdx.x;
    if (i >= (size_t)NB * C * HW) return;
    int s = (int)(i % HW);
    size_t t = i / HW;
    int c = (int)(t % C);
    int n = (int)(t / C);
    float m = g_mean[n * GRP + (c >> 4)];
    float r = g_rstd[n * GRP + (c >> 4)];
    float v = (x[i] - m) * r * gns[c] + gnb[c];
    g_seq_bf[((size_t)n * HW + s) * C + c] = __float2bfloat16(v);
}

// ---------------- fp32 -> bf16 weight convert ----------------
__global__ void convert_kernel(const float* __restrict__ src, int dstid, int count) {
    int i = blockIdx.x * blockDim.x + threadIdx.x;
    if (i < count) bufb(dstid)[i] = __float2bfloat16(src[i]);
}

// ---------------- bf16 tensor-core GEMM, cp.async 2-stage pipeline ----------------
// Out[m][n] = alpha * sum_k A[m][k] * (TRANSB ? B[n][k] : B[k][n]) + bias[n]
// BM=BN=128, BK=32, 256 threads (8 warps: 4x2), warp tile 32x64.
#define SKB 40    // [rows][k] tile row stride (halves): 32 + 8 pad
#define SNB 136   // [k][n] tile row stride (halves): 128 + 8 pad
#define ABUF_H (128 * SKB)          // 5120 halves per stage

template <bool TRANSB, bool OUT_BF16>
__global__ void __launch_bounds__(256, 2) mma_gemm(
    int aid, long long aoff, int bid, long long boff, int cid,
    int K, int lda, int ldb, int ldc,
    long long sA, long long sB, long long sC,
    const float* bias, float alpha) {

    __shared__ __align__(16) __nv_bfloat16 As[2][ABUF_H];
    __shared__ __align__(16) __nv_bfloat16 Bs[2][ABUF_H];  // TRANSB: [n][k]; else [k][n]

    const __nv_bfloat16* A = bufb(aid) + aoff + (size_t)blockIdx.z * sA;
    const __nv_bfloat16* B = bufb(bid) + boff + (size_t)blockIdx.z * sB;

    int m0 = blockIdx.y * 128;
    int n0 = blockIdx.x * 128;
    int tid  = threadIdx.x;
    int warp = tid >> 5, lane = tid & 31;
    int wm = (warp & 3) * 32;
    int wn = (warp >> 2) * 64;
    int lrow = lane & 7, lgrp = lane >> 3;

    unsigned as_base = (unsigned)__cvta_generic_to_shared(&As[0][0]);
    unsigned bs_base = (unsigned)__cvta_generic_to_shared(&Bs[0][0]);

    // per-thread cp.async coordinates
    const int ar0 = tid >> 2,          ac0 = (tid & 3) * 8;          // A / TRANSB-B: 128x32
    const int ar1 = (tid + 256) >> 2,  ac1 = ((tid + 256) & 3) * 8;
    const int kr0 = tid >> 4,          nc0 = (tid & 15) * 8;         // [k][n] B: 32x128
    const int kr1 = (tid + 256) >> 4,  nc1 = ((tid + 256) & 15) * 8;

    // ldmatrix fragment offsets (bytes within one stage)
    unsigned aoffs[2][2], boffs[2][4];
    #pragma unroll
    for (int ks = 0; ks < 2; ks++) {
        #pragma unroll
        for (int mf = 0; mf < 2; mf++) {
            int row = wm + mf * 16 + (lgrp & 1) * 8 + lrow;
            int kof = ks * 16 + (lgrp >> 1) * 8;
            aoffs[ks][mf] = (unsigned)(row * SKB + kof) * 2u;
        }
        #pragma unroll
        for (int np = 0; np < 4; np++) {
            if (TRANSB) {
                int nn  = wn + np * 16 + (lgrp >> 1) * 8 + lrow;
                int kof = ks * 16 + (lgrp & 1) * 8;
                boffs[ks][np] = (unsigned)(nn * SKB + kof) * 2u;
            } else {
                int kk = ks * 16 + (lgrp & 1) * 8 + lrow;
                int nn = wn + np * 16 + (lgrp >> 1) * 8;
                boffs[ks][np] = (unsigned)(kk * SNB + nn) * 2u;
            }
        }
    }

    float acc[2][8][4];
    #pragma unroll
    for (int mf = 0; mf < 2; mf++)
        #pragma unroll
        for (int nf = 0; nf < 8; nf++)
            #pragma unroll
            for (int r = 0; r < 4; r++) acc[mf][nf][r] = 0.f;

    auto issue = [&](int buf, int k0) {
        unsigned ad = as_base + (unsigned)(buf * ABUF_H * 2);
        cpa16(ad + (unsigned)(ar0 * SKB + ac0) * 2u, &A[(size_t)(m0 + ar0) * lda + k0 + ac0]);
        cpa16(ad + (unsigned)(ar1 * SKB + ac1) * 2u, &A[(size_t)(m0 + ar1) * lda + k0 + ac1]);
        unsigned bd = bs_base + (unsigned)(buf * ABUF_H * 2);
        if (TRANSB) {
            cpa16(bd + (unsigned)(ar0 * SKB + ac0) * 2u, &B[(size_t)(n0 + ar0) * ldb + k0 + ac0]);
            cpa16(bd + (unsigned)(ar1 * SKB + ac1) * 2u, &B[(size_t)(n0 + ar1) * ldb + k0 + ac1]);
        } else {
            cpa16(bd + (unsigned)(kr0 * SNB + nc0) * 2u, &B[(size_t)(k0 + kr0) * ldb + n0 + nc0]);
            cpa16(bd + (unsigned)(kr1 * SNB + nc1) * 2u, &B[(size_t)(k0 + kr1) * ldb + n0 + nc1]);
        }
    };

    const int NSTEP = K / 32;
    issue(0, 0);
    cpa_commit();

    int buf = 0;
    for (int it = 0; it < NSTEP; it++) {
        if (it + 1 < NSTEP) {
            issue(buf ^ 1, (it + 1) * 32);
            cpa_commit();
            cpa_wait<1>();
        } else {
            cpa_wait<0>();
        }
        __syncthreads();

        unsigned ab = as_base + (unsigned)(buf * ABUF_H * 2);
        unsigned bb = bs_base + (unsigned)(buf * ABUF_H * 2);
        #pragma unroll
        for (int ks = 0; ks < 2; ks++) {
            unsigned a[2][4], b[4][4];
            #pragma unroll
            for (int mf = 0; mf < 2; mf++)
                asm volatile("ldmatrix.sync.aligned.m8n8.x4.shared.b16 {%0,%1,%2,%3}, [%4];"
                             : "=r"(a[mf][0]), "=r"(a[mf][1]), "=r"(a[mf][2]), "=r"(a[mf][3])
                             : "r"(ab + aoffs[ks][mf]));
            #pragma unroll
            for (int np = 0; np < 4; np++) {
                if (TRANSB)
                    asm volatile("ldmatrix.sync.aligned.m8n8.x4.shared.b16 {%0,%1,%2,%3}, [%4];"
                                 : "=r"(b[np][0]), "=r"(b[np][1]), "=r"(b[np][2]), "=r"(b[np][3])
                                 : "r"(bb + boffs[ks][np]));
                else
                    asm volatile("ldmatrix.sync.aligned.m8n8.x4.trans.shared.b16 {%0,%1,%2,%3}, [%4];"
                                 : "=r"(b[np][0]), "=r"(b[np][1]), "=r"(b[np][2]), "=r"(b[np][3])
                                 : "r"(bb + boffs[ks][np]));
            }
            #pragma unroll
            for (int mf = 0; mf < 2; mf++)
                #pragma unroll
                for (int np = 0; np < 4; np++) {
                    #pragma unroll
                    for (int h = 0; h < 2; h++) {
                        float* c = acc[mf][np * 2 + h];
                        asm volatile(
                            "mma.sync.aligned.m16n8k16.row.col.f32.bf16.bf16.f32 "
                            "{%0,%1,%2,%3}, {%4,%5,%6,%7}, {%8,%9}, {%0,%1,%2,%3};"
                            : "+f"(c[0]), "+f"(c[1]), "+f"(c[2]), "+f"(c[3])
                            : "r"(a[mf][0]), "r"(a[mf][1]), "r"(a[mf][2]), "r"(a[mf][3]),
                              "r"(b[np][h * 2]), "r"(b[np][h * 2 + 1]));
                    }
                }
        }
        buf ^= 1;
        __syncthreads();
    }

    // ---- epilogue ----
    #pragma unroll
    for (int mf = 0; mf < 2; mf++) {
        #pragma unroll
        for (int nf = 0; nf < 8; nf++) {
            int r0 = m0 + wm + mf * 16 + (lane >> 2);
            int cc = n0 + wn + nf * 8 + (lane & 3) * 2;
            float* c = acc[mf][nf];
            float b0 = 0.f, b1 = 0.f;
            if (bias) { b0 = bias[cc]; b1 = bias[cc + 1]; }
            float v0 = c[0] * alpha + b0, v1 = c[1] * alpha + b1;
            float v2 = c[2] * alpha + b0, v3 = c[3] * alpha + b1;
            if (OUT_BF16) {
                __nv_bfloat16* O = bufb(cid) + (size_t)blockIdx.z * sC;
                *(__nv_bfloat162*)&O[(size_t)r0 * ldc + cc] =
                    __nv_bfloat162(__float2bfloat16(v0), __float2bfloat16(v1));
                *(__nv_bfloat162*)&O[(size_t)(r0 + 8) * ldc + cc] =
                    __nv_bfloat162(__float2bfloat16(v2), __float2bfloat16(v3));
            } else {
                float* O = buff(cid) + (size_t)blockIdx.z * sC;   // device-side resolve!
                *(float2*)&O[(size_t)r0 * ldc + cc] = make_float2(v0, v1);
                *(float2*)&O[(size_t)(r0 + 8) * ldc + cc] = make_float2(v2, v3);
            }
        }
    }
}

// ---------------- softmax in place on bf16 rows of g_attn_bf ----------------
__global__ void softmax_bf_kernel() {
    __shared__ float red[8];
    __shared__ float row[HW];
    size_t r = blockIdx.x;
    __nv_bfloat16* p = g_attn_bf + r * (size_t)HW;
    int tid = threadIdx.x;

    float mx = -INFINITY;
    for (int i = tid * 2; i < HW; i += 512) {
        __nv_bfloat162 v2 = *(const __nv_bfloat162*)&p[i];
        float a = __bfloat162float(v2.x), b = __bfloat162float(v2.y);
        row[i] = a; row[i + 1] = b;
        mx = fmaxf(mx, fmaxf(a, b));
    }
    for (int of = 16; of > 0; of >>= 1) mx = fmaxf(mx, __shfl_down_sync(0xffffffffu, mx, of));
    if ((tid & 31) == 0) red[tid >> 5] = mx;
    __syncthreads();
    if (tid == 0) {
        mx = red[0];
        for (int i = 1; i < 8; i++) mx = fmaxf(mx, red[i]);
        red[0] = mx;
    }
    __syncthreads();
    mx = red[0];
    __syncthreads();

    float sum = 0.f;
    for (int i = tid; i < HW; i += 256) {
        float e = __expf(row[i] - mx);
        row[i] = e;
        sum += e;
    }
    for (int of = 16; of > 0; of >>= 1) sum += __shfl_down_sync(0xffffffffu, sum, of);
    if ((tid & 31) == 0) red[tid >> 5] = sum;
    __syncthreads();
    if (tid == 0) {
        sum = 0.f;
        for (int i = 0; i < 8; i++) sum += red[i];
        red[0] = sum;
    }
    __syncthreads();
    float inv = 1.f / red[0];

    for (int i = tid * 2; i < HW; i += 512) {
        *(__nv_bfloat162*)&p[i] = __nv_bfloat162(
            __float2bfloat16(row[i] * inv), __float2bfloat16(row[i + 1] * inv));
    }
}

// ---------------- epilogue: out[n][c][s] = g_proj[n][s][c] + x[n][c][s] --------
__global__ void out_epilogue_naive(const float* __restrict__ x, float* __restrict__ y) {
    size_t i = (size_t)blockIdx.x * blockDim.x + threadIdx.x;
    if (i >= (size_t)NB * C * HW) return;
    int s = (int)(i % HW);
    size_t t = i / HW;
    int c = (int)(t % C);
    int n = (int)(t / C);
    y[i] = g_proj[((size_t)n * HW + s) * C + c] + x[i];
}

extern "C" void kernel_launch(void* const* d_in, const int* in_sizes, int n_in,
                              void* d_out, int out_size) {
    const float* x = 0; const float* w_in = 0; const float* w_out = 0; const float* b_in = 0;
    const float* v512[3] = {0, 0, 0}; int n512 = 0;
    for (int i = 0; i < n_in; i++) {
        const float* p = (const float*)d_in[i];
        switch (in_sizes[i]) {
            case 8388608: x = p; break;
            case 786432:  w_in = p; break;
            case 262144:  w_out = p; break;
            case 1536:    b_in = p; break;
            case 512:     if (n512 < 3) v512[n512++] = p; break;
            default: break;
        }
    }
    const float* gns   = v512[0];
    const float* gnb   = v512[1];
    const float* b_out = v512[2];
    float* out = (float*)d_out;

    const size_t TOT = (size_t)NB * C * HW;

    gn_stats_kernel<<<dim3(GRP, NB), 256>>>(x);
    gn_apply_naive<<<(unsigned)((TOT + 255) / 256), 256>>>(x, gns, gnb);
    convert_kernel<<<(D3 * C + 255) / 256, 256>>>(w_in, BF_WIN, D3 * C);
    convert_kernel<<<(C * C + 255) / 256, 256>>>(w_out, BF_WOUT, C * C);

    // QKV (bf16 out)
    mma_gemm<true, true><<<dim3(D3 / 128, HW / 128, NB), 256>>>(
        BF_SEQ, 0LL, BF_WIN, 0LL, BF_QKV,
        C, C, C, D3,
        (long long)HW * C, 0LL, (long long)HW * D3, b_in, 1.0f);

    // scores -> bf16 directly into g_attn_bf
    mma_gemm<true, true><<<dim3(HW / 128, HW / 128, NB), 256>>>(
        BF_QKV, 0LL, BF_QKV, (long long)C, BF_ATTN,
        C, D3, D3, HW,
        (long long)HW * D3, (long long)HW * D3, (long long)HW * HW,
        (const float*)0, rsqrtf((float)C));

    // softmax in place (bf16)
    softmax_bf_kernel<<<NB * HW, 256>>>();

    // att = attn @ v  (bf16 out)
    mma_gemm<false, true><<<dim3(C / 128, HW / 128, NB), 256>>>(
        BF_ATTN, 0LL, BF_QKV, (long long)(2 * C), BF_ATT,
        HW, HW, D3, C,
        (long long)HW * HW, (long long)HW * D3, (long long)HW * C,
        (const float*)0, 1.0f);

    // proj (fp32 out -> buff(0) == g_proj, resolved in device code)
    mma_gemm<true, false><<<dim3(C / 128, HW / 128, NB), 256>>>(
        BF_ATT, 0LL, BF_WOUT, 0LL, /*cid=*/0,
        C, C, C, C,
        (long long)HW * C, 0LL, (long long)HW * C, b_out, 1.0f);

    out_epilogue_naive<<<(unsigned)((TOT + 255) / 256), 256>>>(x, out);
}